// round 1
// baseline (speedup 1.0000x reference)
#include <cuda_runtime.h>
#include <cstdint>

#define VV 8000
#define DD 128
#define UU 256
#define BB 32
#define SS 256
#define H3 768
#define MR 8192   // B*S

// ---------------- scratch (static device allocations; no cudaMalloc) ---------
__device__ float g_x[MR * DD];
__device__ float g_xzf[MR * H3];
__device__ float g_xzb[MR * H3];
__device__ float g_uktf[H3 * UU];
__device__ float g_uktb[H3 * UU];
__device__ float g_hcat[MR * 2 * UU];
__device__ float g_z1[MR * VV];
__device__ float g_cwf[DD * H3];
__device__ float g_cwb[DD * H3];
__device__ float g_cw1[2 * UU * VV];
__device__ float g_cw2[VV * VV];

__device__ __forceinline__ float rna_tf32(float x) {
    uint32_t u;
    asm("cvt.rna.tf32.f32 %0, %1;" : "=r"(u) : "f"(x));
    return __uint_as_float(u);
}

// ---------------- elementwise rna convert (vectorized) -----------------------
__global__ void cvt_rna4(const float4* __restrict__ in, float4* __restrict__ out, int n4) {
    int i = blockIdx.x * 256 + threadIdx.x;
    if (i < n4) {
        float4 v = in[i];
        v.x = rna_tf32(v.x); v.y = rna_tf32(v.y);
        v.z = rna_tf32(v.z); v.w = rna_tf32(v.w);
        out[i] = v;
    }
}

// ---------------- U transpose: [256][768] -> [768][256] ----------------------
__global__ void transpose_u(const float* __restrict__ Um, float* __restrict__ Ut) {
    int i = blockIdx.x * 256 + threadIdx.x;
    if (i < UU * H3) {
        int k = i / H3, c = i % H3;
        Ut[c * UU + k] = Um[i];
    }
}

// ---------------- embedding gather (rounded: feeds a tf32 GEMM) --------------
__global__ void embed_kernel(const int* __restrict__ tokens, const float* __restrict__ emb,
                             float* __restrict__ x) {
    int row = blockIdx.x;     // row = b*S + s
    int t = threadIdx.x;      // 0..127
    int tok = tokens[row];
    x[(size_t)row * DD + t] = rna_tf32(emb[(size_t)tok * DD + t]);
}

// ---------------- tf32 GEMM: C[M,N] = A[M,K] @ B[K,N] + bias[N] --------------
#define BM 128
#define BN 128
#define BKK 16
#define AST 20    // A smem row stride (floats) -> conflict-free fragment loads
#define BST 136   // B smem row stride (floats) -> conflict-free fragment loads

__global__ void __launch_bounds__(256) gemm_tf32(
    const float* __restrict__ A, const float* __restrict__ Bm,
    const float* __restrict__ bias, float* __restrict__ C,
    int M, int N, int K, int round_out)
{
    __shared__ __align__(16) float As[2][BM * AST];
    __shared__ __align__(16) float Bs[2][BKK * BST];

    const int nbx = (N + BN - 1) / BN;
    const int nby = M / BM;
    const int CW = 16;                     // N-chunk width for L2-friendly raster
    int bid = blockIdx.x;
    int per = CW * nby;
    int chunk = bid / per;
    int rem = bid - chunk * per;
    int cw = min(CW, nbx - chunk * CW);
    int by = rem / cw;
    int bx = chunk * CW + (rem - by * cw);
    int m0 = by * BM, n0 = bx * BN;

    int tid = threadIdx.x;
    int lane = tid & 31;
    int wid = tid >> 5;
    int wm = wid >> 2;   // 0..1  (64 rows per warp)
    int wn = wid & 3;    // 0..3  (32 cols per warp)

    uint32_t sA = (uint32_t)__cvta_generic_to_shared(&As[0][0]);
    uint32_t sB = (uint32_t)__cvta_generic_to_shared(&Bs[0][0]);

    // A tile: 128x16 = 512 16B-chunks; thread handles chunk tid and tid+256
    int arow0 = tid >> 2;              int acc0c = (tid & 3) * 4;
    int arow1 = (tid + 256) >> 2;      // same (tid&3)
    // B tile: 16x128 = 512 16B-chunks
    int brow0 = tid >> 5;              int bcc0 = (tid & 31) * 4;
    int brow1 = (tid + 256) >> 5;      // same col

    float acc[4][4][4];
#pragma unroll
    for (int a = 0; a < 4; a++)
#pragma unroll
        for (int b = 0; b < 4; b++)
#pragma unroll
            for (int c = 0; c < 4; c++) acc[a][b][c] = 0.f;

    const int KT = K / BKK;

    auto issue = [&](int kt, int buf) {
        int k0 = kt * BKK;
        {
            const float* g0 = A + (size_t)(m0 + arow0) * K + k0 + acc0c;
            const float* g1 = A + (size_t)(m0 + arow1) * K + k0 + acc0c;
            uint32_t d0 = sA + (uint32_t)(buf * BM * AST + arow0 * AST + acc0c) * 4u;
            uint32_t d1 = sA + (uint32_t)(buf * BM * AST + arow1 * AST + acc0c) * 4u;
            asm volatile("cp.async.cg.shared.global [%0],[%1],16;\n" :: "r"(d0), "l"(g0));
            asm volatile("cp.async.cg.shared.global [%0],[%1],16;\n" :: "r"(d1), "l"(g1));
        }
        {
            int n0c = n0 + bcc0;
            int gcol = (n0c < N) ? n0c : (N - 4);
            int sz = (n0c < N) ? 16 : 0;   // zero-fill OOB columns
            const float* g0 = Bm + (size_t)(k0 + brow0) * N + gcol;
            const float* g1 = Bm + (size_t)(k0 + brow1) * N + gcol;
            uint32_t d0 = sB + (uint32_t)(buf * BKK * BST + brow0 * BST + bcc0) * 4u;
            uint32_t d1 = sB + (uint32_t)(buf * BKK * BST + brow1 * BST + bcc0) * 4u;
            asm volatile("cp.async.cg.shared.global [%0],[%1],16,%2;\n" :: "r"(d0), "l"(g0), "r"(sz));
            asm volatile("cp.async.cg.shared.global [%0],[%1],16,%2;\n" :: "r"(d1), "l"(g1), "r"(sz));
        }
    };

    auto docompute = [&](int buf) {
        const float* Ab = &As[buf][0];
        const float* Bb = &Bs[buf][0];
#pragma unroll
        for (int kk = 0; kk < 2; kk++) {
            uint32_t af[4][4];
#pragma unroll
            for (int mi = 0; mi < 4; mi++) {
                int r = wm * 64 + mi * 16 + (lane >> 2);
                int c = kk * 8 + (lane & 3);
                af[mi][0] = __float_as_uint(Ab[r * AST + c]);
                af[mi][1] = __float_as_uint(Ab[(r + 8) * AST + c]);
                af[mi][2] = __float_as_uint(Ab[r * AST + c + 4]);
                af[mi][3] = __float_as_uint(Ab[(r + 8) * AST + c + 4]);
            }
            uint32_t bf[4][2];
#pragma unroll
            for (int ni = 0; ni < 4; ni++) {
                int cc = wn * 32 + ni * 8 + (lane >> 2);
                int kb = kk * 8 + (lane & 3);
                bf[ni][0] = __float_as_uint(Bb[kb * BST + cc]);
                bf[ni][1] = __float_as_uint(Bb[(kb + 4) * BST + cc]);
            }
#pragma unroll
            for (int mi = 0; mi < 4; mi++)
#pragma unroll
                for (int ni = 0; ni < 4; ni++) {
                    asm volatile(
                        "mma.sync.aligned.m16n8k8.row.col.f32.tf32.tf32.f32 "
                        "{%0,%1,%2,%3},{%4,%5,%6,%7},{%8,%9},{%0,%1,%2,%3};\n"
                        : "+f"(acc[mi][ni][0]), "+f"(acc[mi][ni][1]),
                          "+f"(acc[mi][ni][2]), "+f"(acc[mi][ni][3])
                        : "r"(af[mi][0]), "r"(af[mi][1]), "r"(af[mi][2]), "r"(af[mi][3]),
                          "r"(bf[ni][0]), "r"(bf[ni][1]));
                }
        }
    };

    issue(0, 0);
    asm volatile("cp.async.commit_group;\n");
#pragma unroll 1
    for (int kt = 0; kt < KT; kt++) {
        int cur = kt & 1;
        if (kt + 1 < KT) {
            issue(kt + 1, cur ^ 1);
            asm volatile("cp.async.commit_group;\n");
            asm volatile("cp.async.wait_group 1;\n");
        } else {
            asm volatile("cp.async.wait_group 0;\n");
        }
        __syncthreads();
        docompute(cur);
        __syncthreads();
    }

    // epilogue
#pragma unroll
    for (int mi = 0; mi < 4; mi++) {
        int r = m0 + wm * 64 + mi * 16 + (lane >> 2);
#pragma unroll
        for (int ni = 0; ni < 4; ni++) {
            int c = n0 + wn * 32 + ni * 8 + (lane & 3) * 2;
            if (c < N) {
                float b0v = bias[c], b1v = bias[c + 1];
                float v0 = acc[mi][ni][0] + b0v;
                float v1 = acc[mi][ni][1] + b1v;
                float v2 = acc[mi][ni][2] + b0v;
                float v3 = acc[mi][ni][3] + b1v;
                if (round_out) {
                    v0 = rna_tf32(v0); v1 = rna_tf32(v1);
                    v2 = rna_tf32(v2); v3 = rna_tf32(v3);
                }
                *reinterpret_cast<float2*>(&C[(size_t)r * N + c]) = make_float2(v0, v1);
                *reinterpret_cast<float2*>(&C[(size_t)(r + 8) * N + c]) = make_float2(v2, v3);
            }
        }
    }
}

// ---------------- bidirectional masked GRU scan -------------------------------
// grid (16, 2): x = batch pair, y = direction. 256 threads, thread j owns u-col j.
__global__ void __launch_bounds__(256) gru_scan(
    const float* __restrict__ xzf, const float* __restrict__ xzb,
    const float* __restrict__ uktf, const float* __restrict__ uktb,
    const float* __restrict__ bf1, const float* __restrict__ bb1,
    const int* __restrict__ tokens, float* __restrict__ hcat)
{
    int dir = blockIdx.y;
    const float* xz  = dir ? xzb  : xzf;
    const float* ukt = dir ? uktb : uktf;
    const float* bv  = dir ? bb1  : bf1;    // b[1] row (768)
    int b0 = blockIdx.x * 2;
    int j = threadIdx.x;

    __shared__ float hs[2][UU];
    hs[0][j] = 0.f; hs[1][j] = 0.f;

    float bz = bv[j], br = bv[UU + j], bh = bv[2 * UU + j];
    const float4* uz = reinterpret_cast<const float4*>(ukt + (size_t)j * UU);
    const float4* ur = reinterpret_cast<const float4*>(ukt + (size_t)(UU + j) * UU);
    const float4* uh = reinterpret_cast<const float4*>(ukt + (size_t)(2 * UU + j) * UU);
    __syncthreads();

    for (int i = 0; i < SS; i++) {
        int s = dir ? (SS - 1 - i) : i;
        size_t r0 = (size_t)b0 * SS + s;
        size_t r1 = r0 + SS;

        float az0 = 0.f, ar0 = 0.f, ah0 = 0.f, az1 = 0.f, ar1 = 0.f, ah1 = 0.f;
        const float4* h0 = reinterpret_cast<const float4*>(hs[0]);
        const float4* h1 = reinterpret_cast<const float4*>(hs[1]);
#pragma unroll 8
        for (int k = 0; k < UU / 4; k++) {
            float4 wz = uz[k], wr = ur[k], wh = uh[k];
            float4 p = h0[k], q = h1[k];
            az0 += wz.x * p.x + wz.y * p.y + wz.z * p.z + wz.w * p.w;
            ar0 += wr.x * p.x + wr.y * p.y + wr.z * p.z + wr.w * p.w;
            ah0 += wh.x * p.x + wh.y * p.y + wh.z * p.z + wh.w * p.w;
            az1 += wz.x * q.x + wz.y * q.y + wz.z * q.z + wz.w * q.w;
            ar1 += wr.x * q.x + wr.y * q.y + wr.z * q.z + wr.w * q.w;
            ah1 += wh.x * q.x + wh.y * q.y + wh.z * q.z + wh.w * q.w;
        }

        float hold0 = hs[0][j], hold1 = hs[1][j];
        const float* x0 = xz + r0 * H3;
        const float* x1 = xz + r1 * H3;

        float z0 = 1.f / (1.f + expf(-(x0[j] + az0 + bz)));
        float g0 = 1.f / (1.f + expf(-(x0[UU + j] + ar0 + br)));
        float c0 = tanhf(x0[2 * UU + j] + g0 * (ah0 + bh));
        float hn0 = z0 * hold0 + (1.f - z0) * c0;
        if (tokens[r0] == 0) hn0 = hold0;

        float z1v = 1.f / (1.f + expf(-(x1[j] + az1 + bz)));
        float g1 = 1.f / (1.f + expf(-(x1[UU + j] + ar1 + br)));
        float c1 = tanhf(x1[2 * UU + j] + g1 * (ah1 + bh));
        float hn1 = z1v * hold1 + (1.f - z1v) * c1;
        if (tokens[r1] == 0) hn1 = hold1;

        __syncthreads();
        hs[0][j] = hn0; hs[1][j] = hn1;
        hcat[r0 * (2 * UU) + dir * UU + j] = rna_tf32(hn0);  // feeds tf32 GEMM1
        hcat[r1 * (2 * UU) + dir * UU + j] = rna_tf32(hn1);
        __syncthreads();
    }
}

// ---------------- host launcher ----------------------------------------------
extern "C" void kernel_launch(void* const* d_in, const int* in_sizes, int n_in,
                              void* d_out, int out_size)
{
    const int*   tokens = (const int*)d_in[0];
    const float* emb    = (const float*)d_in[1];
    const float* W_f    = (const float*)d_in[2];
    const float* U_f    = (const float*)d_in[3];
    const float* b_f    = (const float*)d_in[4];
    const float* W_b    = (const float*)d_in[5];
    const float* U_b    = (const float*)d_in[6];
    const float* b_b    = (const float*)d_in[7];
    const float* W1     = (const float*)d_in[8];
    const float* b1     = (const float*)d_in[9];
    const float* W2     = (const float*)d_in[10];
    const float* b2     = (const float*)d_in[11];
    float* out = (float*)d_out;

    float *x, *xzf, *xzb, *uktf, *uktb, *hcat, *z1, *cwf, *cwb, *cw1, *cw2;
    cudaGetSymbolAddress((void**)&x,    g_x);
    cudaGetSymbolAddress((void**)&xzf,  g_xzf);
    cudaGetSymbolAddress((void**)&xzb,  g_xzb);
    cudaGetSymbolAddress((void**)&uktf, g_uktf);
    cudaGetSymbolAddress((void**)&uktb, g_uktb);
    cudaGetSymbolAddress((void**)&hcat, g_hcat);
    cudaGetSymbolAddress((void**)&z1,   g_z1);
    cudaGetSymbolAddress((void**)&cwf,  g_cwf);
    cudaGetSymbolAddress((void**)&cwb,  g_cwb);
    cudaGetSymbolAddress((void**)&cw1,  g_cw1);
    cudaGetSymbolAddress((void**)&cw2,  g_cw2);

    // 1) round weights to tf32 (rna) into scratch
    {
        int n4 = DD * H3 / 4;
        cvt_rna4<<<(n4 + 255) / 256, 256>>>((const float4*)W_f, (float4*)cwf, n4);
        cvt_rna4<<<(n4 + 255) / 256, 256>>>((const float4*)W_b, (float4*)cwb, n4);
    }
    {
        int n4 = 2 * UU * VV / 4;
        cvt_rna4<<<(n4 + 255) / 256, 256>>>((const float4*)W1, (float4*)cw1, n4);
    }
    {
        int n4 = VV * VV / 4;
        cvt_rna4<<<(n4 + 255) / 256, 256>>>((const float4*)W2, (float4*)cw2, n4);
    }

    // 2) transpose recurrent weights (kept exact fp32 for the scan)
    {
        int n = UU * H3;
        transpose_u<<<(n + 255) / 256, 256>>>(U_f, uktf);
        transpose_u<<<(n + 255) / 256, 256>>>(U_b, uktb);
    }

    // 3) embedding gather (rounded)
    embed_kernel<<<MR, DD>>>(tokens, emb, x);

    // 4) xz projections: [8192,128] @ [128,768] + b[0]
    {
        int nbx = H3 / BN, nby = MR / BM;   // 6 x 64
        gemm_tf32<<<nbx * nby, 256>>>(x, cwf, b_f,       xzf, MR, H3, DD, 0);
        gemm_tf32<<<nbx * nby, 256>>>(x, cwb, b_b,       xzb, MR, H3, DD, 0);
    }

    // 5) bidirectional GRU scan
    gru_scan<<<dim3(BB / 2, 2), UU>>>(xzf, xzb, uktf, uktb, b_f + H3, b_b + H3,
                                      tokens, hcat);

    // 6) z1 = hcat @ W1 + b1  (store rounded: feeds next tf32 GEMM)
    {
        int nbx = (VV + BN - 1) / BN, nby = MR / BM;  // 63 x 64
        gemm_tf32<<<nbx * nby, 256>>>(hcat, cw1, b1, z1, MR, VV, 2 * UU, 1);
        // 7) logits = z1 @ W2 + b2 -> output (full fp32 store)
        gemm_tf32<<<nbx * nby, 256>>>(z1, cw2, b2, out, MR, VV, VV, 0);
    }
}

// round 2
// speedup vs baseline: 1.4741x; 1.4741x over previous
#include <cuda_runtime.h>
#include <cstdint>

#define VV 8000
#define DD 128
#define UU 256
#define BB 32
#define SS 256
#define H3 768
#define MR 8192   // B*S

// ---------------- scratch (static device allocations; no cudaMalloc) ---------
__device__ float g_x[MR * DD];
__device__ float g_xzf[MR * H3];
__device__ float g_xzb[MR * H3];
__device__ float g_uktf[H3 * UU];
__device__ float g_uktb[H3 * UU];
__device__ float g_hcat[MR * 2 * UU];
__device__ float g_cwf[DD * H3];
__device__ float g_cwb[DD * H3];
__device__ float g_cw1[2 * UU * VV];
__device__ float g_cw2[VV * VV];
__device__ float g_wf[2 * UU * VV];   // fused weight W1@W2 [512, 8000]
__device__ float g_bf[VV];            // fused bias b1@W2 + b2
__device__ float g_zb[VV];            // zero bias (never written; zero-init)

__device__ __forceinline__ float rna_tf32(float x) {
    uint32_t u;
    asm("cvt.rna.tf32.f32 %0, %1;" : "=r"(u) : "f"(x));
    return __uint_as_float(u);
}

// ---------------- elementwise rna convert (vectorized) -----------------------
__global__ void cvt_rna4(const float4* __restrict__ in, float4* __restrict__ out, int n4) {
    int i = blockIdx.x * 256 + threadIdx.x;
    if (i < n4) {
        float4 v = in[i];
        v.x = rna_tf32(v.x); v.y = rna_tf32(v.y);
        v.z = rna_tf32(v.z); v.w = rna_tf32(v.w);
        out[i] = v;
    }
}

// ---------------- U transpose: [256][768] -> [768][256] ----------------------
__global__ void transpose_u(const float* __restrict__ Um, float* __restrict__ Ut) {
    int i = blockIdx.x * 256 + threadIdx.x;
    if (i < UU * H3) {
        int k = i / H3, c = i % H3;
        Ut[c * UU + k] = Um[i];
    }
}

// ---------------- embedding gather (rounded: feeds a tf32 GEMM) --------------
__global__ void embed_kernel(const int* __restrict__ tokens, const float* __restrict__ emb,
                             float* __restrict__ x) {
    int row = blockIdx.x;     // row = b*S + s
    int t = threadIdx.x;      // 0..127
    int tok = tokens[row];
    x[(size_t)row * DD + t] = rna_tf32(emb[(size_t)tok * DD + t]);
}

// ---------------- fused bias: bf[n] = b2[n] + sum_v b1[v]*W2[v][n] ------------
__global__ void bias_fuse(const float* __restrict__ b1v, const float* __restrict__ W2m,
                          const float* __restrict__ b2v, float* __restrict__ bf) {
    int n = blockIdx.x * 128 + threadIdx.x;
    if (n >= VV) return;
    float acc = b2v[n];
#pragma unroll 4
    for (int v = 0; v < VV; v++)
        acc += b1v[v] * W2m[(size_t)v * VV + n];
    bf[n] = acc;
}

// ---------------- tf32 GEMM: C[M,N] = A[M,K] @ B[K,N] + bias[N] --------------
#define BM 128
#define BN 128
#define BKK 16
#define AST 20    // A smem row stride (floats) -> conflict-free fragment loads
#define BST 136   // B smem row stride (floats) -> conflict-free fragment loads

__global__ void __launch_bounds__(256) gemm_tf32(
    const float* __restrict__ A, const float* __restrict__ Bm,
    const float* __restrict__ bias, float* __restrict__ C,
    int M, int N, int K, int round_out)
{
    __shared__ __align__(16) float As[2][BM * AST];
    __shared__ __align__(16) float Bs[2][BKK * BST];

    const int nbx = (N + BN - 1) / BN;
    const int nby = M / BM;
    const int CW = 16;                     // N-chunk width for L2-friendly raster
    int bid = blockIdx.x;
    int per = CW * nby;
    int chunk = bid / per;
    int rem = bid - chunk * per;
    int cw = min(CW, nbx - chunk * CW);
    int by = rem / cw;
    int bx = chunk * CW + (rem - by * cw);
    int m0 = by * BM, n0 = bx * BN;

    int tid = threadIdx.x;
    int lane = tid & 31;
    int wid = tid >> 5;
    int wm = wid >> 2;   // 0..1  (64 rows per warp)
    int wn = wid & 3;    // 0..3  (32 cols per warp)

    uint32_t sA = (uint32_t)__cvta_generic_to_shared(&As[0][0]);
    uint32_t sB = (uint32_t)__cvta_generic_to_shared(&Bs[0][0]);

    // A tile: 128x16 = 512 16B-chunks; thread handles chunk tid and tid+256
    int arow0 = tid >> 2;              int acc0c = (tid & 3) * 4;
    int arow1 = (tid + 256) >> 2;      // same (tid&3)
    // B tile: 16x128 = 512 16B-chunks
    int brow0 = tid >> 5;              int bcc0 = (tid & 31) * 4;
    int brow1 = (tid + 256) >> 5;      // same col

    float acc[4][4][4];
#pragma unroll
    for (int a = 0; a < 4; a++)
#pragma unroll
        for (int b = 0; b < 4; b++)
#pragma unroll
            for (int c = 0; c < 4; c++) acc[a][b][c] = 0.f;

    const int KT = K / BKK;

    auto issue = [&](int kt, int buf) {
        int k0 = kt * BKK;
        {
            const float* g0 = A + (size_t)(m0 + arow0) * K + k0 + acc0c;
            const float* g1 = A + (size_t)(m0 + arow1) * K + k0 + acc0c;
            uint32_t d0 = sA + (uint32_t)(buf * BM * AST + arow0 * AST + acc0c) * 4u;
            uint32_t d1 = sA + (uint32_t)(buf * BM * AST + arow1 * AST + acc0c) * 4u;
            asm volatile("cp.async.cg.shared.global [%0],[%1],16;\n" :: "r"(d0), "l"(g0));
            asm volatile("cp.async.cg.shared.global [%0],[%1],16;\n" :: "r"(d1), "l"(g1));
        }
        {
            int n0c = n0 + bcc0;
            int gcol = (n0c < N) ? n0c : (N - 4);
            int sz = (n0c < N) ? 16 : 0;   // zero-fill OOB columns
            const float* g0 = Bm + (size_t)(k0 + brow0) * N + gcol;
            const float* g1 = Bm + (size_t)(k0 + brow1) * N + gcol;
            uint32_t d0 = sB + (uint32_t)(buf * BKK * BST + brow0 * BST + bcc0) * 4u;
            uint32_t d1 = sB + (uint32_t)(buf * BKK * BST + brow1 * BST + bcc0) * 4u;
            asm volatile("cp.async.cg.shared.global [%0],[%1],16,%2;\n" :: "r"(d0), "l"(g0), "r"(sz));
            asm volatile("cp.async.cg.shared.global [%0],[%1],16,%2;\n" :: "r"(d1), "l"(g1), "r"(sz));
        }
    };

    auto docompute = [&](int buf) {
        const float* Ab = &As[buf][0];
        const float* Bb = &Bs[buf][0];
#pragma unroll
        for (int kk = 0; kk < 2; kk++) {
            uint32_t af[4][4];
#pragma unroll
            for (int mi = 0; mi < 4; mi++) {
                int r = wm * 64 + mi * 16 + (lane >> 2);
                int c = kk * 8 + (lane & 3);
                af[mi][0] = __float_as_uint(Ab[r * AST + c]);
                af[mi][1] = __float_as_uint(Ab[(r + 8) * AST + c]);
                af[mi][2] = __float_as_uint(Ab[r * AST + c + 4]);
                af[mi][3] = __float_as_uint(Ab[(r + 8) * AST + c + 4]);
            }
            uint32_t bf[4][2];
#pragma unroll
            for (int ni = 0; ni < 4; ni++) {
                int cc = wn * 32 + ni * 8 + (lane >> 2);
                int kb = kk * 8 + (lane & 3);
                bf[ni][0] = __float_as_uint(Bb[kb * BST + cc]);
                bf[ni][1] = __float_as_uint(Bb[(kb + 4) * BST + cc]);
            }
#pragma unroll
            for (int mi = 0; mi < 4; mi++)
#pragma unroll
                for (int ni = 0; ni < 4; ni++) {
                    asm volatile(
                        "mma.sync.aligned.m16n8k8.row.col.f32.tf32.tf32.f32 "
                        "{%0,%1,%2,%3},{%4,%5,%6,%7},{%8,%9},{%0,%1,%2,%3};\n"
                        : "+f"(acc[mi][ni][0]), "+f"(acc[mi][ni][1]),
                          "+f"(acc[mi][ni][2]), "+f"(acc[mi][ni][3])
                        : "r"(af[mi][0]), "r"(af[mi][1]), "r"(af[mi][2]), "r"(af[mi][3]),
                          "r"(bf[ni][0]), "r"(bf[ni][1]));
                }
        }
    };

    issue(0, 0);
    asm volatile("cp.async.commit_group;\n");
#pragma unroll 1
    for (int kt = 0; kt < KT; kt++) {
        int cur = kt & 1;
        if (kt + 1 < KT) {
            issue(kt + 1, cur ^ 1);
            asm volatile("cp.async.commit_group;\n");
            asm volatile("cp.async.wait_group 1;\n");
        } else {
            asm volatile("cp.async.wait_group 0;\n");
        }
        __syncthreads();
        docompute(cur);
        __syncthreads();
    }

    // epilogue
#pragma unroll
    for (int mi = 0; mi < 4; mi++) {
        int r = m0 + wm * 64 + mi * 16 + (lane >> 2);
#pragma unroll
        for (int ni = 0; ni < 4; ni++) {
            int c = n0 + wn * 32 + ni * 8 + (lane & 3) * 2;
            if (c < N) {
                float b0v = bias[c], b1v = bias[c + 1];
                float v0 = acc[mi][ni][0] + b0v;
                float v1 = acc[mi][ni][1] + b1v;
                float v2 = acc[mi][ni][2] + b0v;
                float v3 = acc[mi][ni][3] + b1v;
                if (round_out) {
                    v0 = rna_tf32(v0); v1 = rna_tf32(v1);
                    v2 = rna_tf32(v2); v3 = rna_tf32(v3);
                }
                *reinterpret_cast<float2*>(&C[(size_t)r * N + c]) = make_float2(v0, v1);
                *reinterpret_cast<float2*>(&C[(size_t)(r + 8) * N + c]) = make_float2(v2, v3);
            }
        }
    }
}

// ---------------- bidirectional masked GRU scan -------------------------------
// grid (16, 2): x = batch pair, y = direction. 256 threads, thread j owns u-col j.
__global__ void __launch_bounds__(256) gru_scan(
    const float* __restrict__ xzf, const float* __restrict__ xzb,
    const float* __restrict__ uktf, const float* __restrict__ uktb,
    const float* __restrict__ bf1, const float* __restrict__ bb1,
    const int* __restrict__ tokens, float* __restrict__ hcat)
{
    int dir = blockIdx.y;
    const float* xz  = dir ? xzb  : xzf;
    const float* ukt = dir ? uktb : uktf;
    const float* bv  = dir ? bb1  : bf1;    // b[1] row (768)
    int b0 = blockIdx.x * 2;
    int j = threadIdx.x;

    __shared__ float hs[2][UU];
    hs[0][j] = 0.f; hs[1][j] = 0.f;

    float bz = bv[j], br = bv[UU + j], bh = bv[2 * UU + j];
    const float4* uz = reinterpret_cast<const float4*>(ukt + (size_t)j * UU);
    const float4* ur = reinterpret_cast<const float4*>(ukt + (size_t)(UU + j) * UU);
    const float4* uh = reinterpret_cast<const float4*>(ukt + (size_t)(2 * UU + j) * UU);
    __syncthreads();

    for (int i = 0; i < SS; i++) {
        int s = dir ? (SS - 1 - i) : i;
        size_t r0 = (size_t)b0 * SS + s;
        size_t r1 = r0 + SS;

        float az0 = 0.f, ar0 = 0.f, ah0 = 0.f, az1 = 0.f, ar1 = 0.f, ah1 = 0.f;
        const float4* h0 = reinterpret_cast<const float4*>(hs[0]);
        const float4* h1 = reinterpret_cast<const float4*>(hs[1]);
#pragma unroll 8
        for (int k = 0; k < UU / 4; k++) {
            float4 wz = uz[k], wr = ur[k], wh = uh[k];
            float4 p = h0[k], q = h1[k];
            az0 += wz.x * p.x + wz.y * p.y + wz.z * p.z + wz.w * p.w;
            ar0 += wr.x * p.x + wr.y * p.y + wr.z * p.z + wr.w * p.w;
            ah0 += wh.x * p.x + wh.y * p.y + wh.z * p.z + wh.w * p.w;
            az1 += wz.x * q.x + wz.y * q.y + wz.z * q.z + wz.w * q.w;
            ar1 += wr.x * q.x + wr.y * q.y + wr.z * q.z + wr.w * q.w;
            ah1 += wh.x * q.x + wh.y * q.y + wh.z * q.z + wh.w * q.w;
        }

        float hold0 = hs[0][j], hold1 = hs[1][j];
        const float* x0 = xz + r0 * H3;
        const float* x1 = xz + r1 * H3;

        float z0 = 1.f / (1.f + expf(-(x0[j] + az0 + bz)));
        float g0 = 1.f / (1.f + expf(-(x0[UU + j] + ar0 + br)));
        float c0 = tanhf(x0[2 * UU + j] + g0 * (ah0 + bh));
        float hn0 = z0 * hold0 + (1.f - z0) * c0;
        if (tokens[r0] == 0) hn0 = hold0;

        float z1v = 1.f / (1.f + expf(-(x1[j] + az1 + bz)));
        float g1 = 1.f / (1.f + expf(-(x1[UU + j] + ar1 + br)));
        float c1 = tanhf(x1[2 * UU + j] + g1 * (ah1 + bh));
        float hn1 = z1v * hold1 + (1.f - z1v) * c1;
        if (tokens[r1] == 0) hn1 = hold1;

        __syncthreads();
        hs[0][j] = hn0; hs[1][j] = hn1;
        hcat[r0 * (2 * UU) + dir * UU + j] = rna_tf32(hn0);  // feeds tf32 GEMM
        hcat[r1 * (2 * UU) + dir * UU + j] = rna_tf32(hn1);
        __syncthreads();
    }
}

// ---------------- host launcher ----------------------------------------------
extern "C" void kernel_launch(void* const* d_in, const int* in_sizes, int n_in,
                              void* d_out, int out_size)
{
    const int*   tokens = (const int*)d_in[0];
    const float* emb    = (const float*)d_in[1];
    const float* W_f    = (const float*)d_in[2];
    const float* U_f    = (const float*)d_in[3];
    const float* b_f    = (const float*)d_in[4];
    const float* W_b    = (const float*)d_in[5];
    const float* U_b    = (const float*)d_in[6];
    const float* b_b    = (const float*)d_in[7];
    const float* W1     = (const float*)d_in[8];
    const float* b1     = (const float*)d_in[9];
    const float* W2     = (const float*)d_in[10];
    const float* b2     = (const float*)d_in[11];
    float* out = (float*)d_out;

    float *x, *xzf, *xzb, *uktf, *uktb, *hcat, *cwf, *cwb, *cw1, *cw2, *wf, *bfv, *zb;
    cudaGetSymbolAddress((void**)&x,    g_x);
    cudaGetSymbolAddress((void**)&xzf,  g_xzf);
    cudaGetSymbolAddress((void**)&xzb,  g_xzb);
    cudaGetSymbolAddress((void**)&uktf, g_uktf);
    cudaGetSymbolAddress((void**)&uktb, g_uktb);
    cudaGetSymbolAddress((void**)&hcat, g_hcat);
    cudaGetSymbolAddress((void**)&cwf,  g_cwf);
    cudaGetSymbolAddress((void**)&cwb,  g_cwb);
    cudaGetSymbolAddress((void**)&cw1,  g_cw1);
    cudaGetSymbolAddress((void**)&cw2,  g_cw2);
    cudaGetSymbolAddress((void**)&wf,   g_wf);
    cudaGetSymbolAddress((void**)&bfv,  g_bf);
    cudaGetSymbolAddress((void**)&zb,   g_zb);

    // 1) round weights to tf32 (rna) into scratch
    {
        int n4 = DD * H3 / 4;
        cvt_rna4<<<(n4 + 255) / 256, 256>>>((const float4*)W_f, (float4*)cwf, n4);
        cvt_rna4<<<(n4 + 255) / 256, 256>>>((const float4*)W_b, (float4*)cwb, n4);
    }
    {
        int n4 = 2 * UU * VV / 4;
        cvt_rna4<<<(n4 + 255) / 256, 256>>>((const float4*)W1, (float4*)cw1, n4);
    }
    {
        int n4 = VV * VV / 4;
        cvt_rna4<<<(n4 + 255) / 256, 256>>>((const float4*)W2, (float4*)cw2, n4);
    }

    // 2) fused output weight: Wf = W1 @ W2  [512, 8000], rounded for next GEMM
    {
        int nbx = (VV + BN - 1) / BN;           // 63
        int nby = (2 * UU) / BM;                // 4
        gemm_tf32<<<nbx * nby, 256>>>(cw1, cw2, zb, wf, 2 * UU, VV, VV, 1);
    }
    // fused bias: bf = b1 @ W2 + b2 (exact fp32)
    bias_fuse<<<(VV + 127) / 128, 128>>>(b1, W2, b2, bfv);

    // 3) transpose recurrent weights (kept exact fp32 for the scan)
    {
        int n = UU * H3;
        transpose_u<<<(n + 255) / 256, 256>>>(U_f, uktf);
        transpose_u<<<(n + 255) / 256, 256>>>(U_b, uktb);
    }

    // 4) embedding gather (rounded)
    embed_kernel<<<MR, DD>>>(tokens, emb, x);

    // 5) xz projections: [8192,128] @ [128,768] + b[0]
    {
        int nbx = H3 / BN, nby = MR / BM;   // 6 x 64
        gemm_tf32<<<nbx * nby, 256>>>(x, cwf, b_f, xzf, MR, H3, DD, 0);
        gemm_tf32<<<nbx * nby, 256>>>(x, cwb, b_b, xzb, MR, H3, DD, 0);
    }

    // 6) bidirectional GRU scan
    gru_scan<<<dim3(BB / 2, 2), UU>>>(xzf, xzb, uktf, uktb, b_f + H3, b_b + H3,
                                      tokens, hcat);

    // 7) logits = hcat @ Wf + bf -> output
    {
        int nbx = (VV + BN - 1) / BN, nby = MR / BM;  // 63 x 64
        gemm_tf32<<<nbx * nby, 256>>>(hcat, wf, bfv, out, MR, VV, 2 * UU, 0);
    }
}

// round 3
// speedup vs baseline: 3.6922x; 2.5046x over previous
#include <cuda_runtime.h>
#include <cstdint>

#define VV 8000
#define DD 128
#define UU 256
#define BB 32
#define SS 256
#define H3 768
#define MR 8192   // B*S

// ---------------- scratch (static device allocations; no cudaMalloc) ---------
__device__ float g_x[MR * DD];
__device__ float g_xzf[MR * H3];
__device__ float g_xzb[MR * H3];
__device__ float g_hcat[MR * 2 * UU];
__device__ float g_cwf[DD * H3];
__device__ float g_cwb[DD * H3];
__device__ float g_cw1[2 * UU * VV];
__device__ float g_cw2[VV * VV];
__device__ float g_wf[2 * UU * VV];   // fused weight W1@W2 [512, 8000]
__device__ float g_bf[VV];            // fused bias b1@W2 + b2
__device__ float g_bpart[32 * VV];    // bias partial sums
__device__ float g_zb[VV];            // zero bias (never written; zero-init)

__device__ __forceinline__ float rna_tf32(float x) {
    uint32_t u;
    asm("cvt.rna.tf32.f32 %0, %1;" : "=r"(u) : "f"(x));
    return __uint_as_float(u);
}

// packed f32x2 helpers (sm_103a)
__device__ __forceinline__ unsigned long long pack2(float x, float y) {
    unsigned long long r;
    asm("mov.b64 %0, {%1,%2};" : "=l"(r) : "f"(x), "f"(y));
    return r;
}
__device__ __forceinline__ float2 unpack2(unsigned long long v) {
    float2 r;
    asm("mov.b64 {%0,%1}, %2;" : "=f"(r.x), "=f"(r.y) : "l"(v));
    return r;
}
#define FMA2(acc, a, b) \
    asm("fma.rn.f32x2 %0, %1, %2, %0;" : "+l"(acc) : "l"(a), "l"(b))

// ---------------- elementwise rna convert (vectorized) -----------------------
__global__ void cvt_rna4(const float4* __restrict__ in, float4* __restrict__ out, int n4) {
    int i = blockIdx.x * 256 + threadIdx.x;
    if (i < n4) {
        float4 v = in[i];
        v.x = rna_tf32(v.x); v.y = rna_tf32(v.y);
        v.z = rna_tf32(v.z); v.w = rna_tf32(v.w);
        out[i] = v;
    }
}

// ---------------- embedding gather (rounded: feeds a tf32 GEMM) --------------
__global__ void embed_kernel(const int* __restrict__ tokens, const float* __restrict__ emb,
                             float* __restrict__ x) {
    int row = blockIdx.x;     // row = b*S + s
    int t = threadIdx.x;      // 0..127
    int tok = tokens[row];
    x[(size_t)row * DD + t] = rna_tf32(emb[(size_t)tok * DD + t]);
}

// ---------------- fused bias: bf[n] = b2[n] + sum_v b1[v]*W2[v][n] ------------
__global__ void bias_fuse_part(const float* __restrict__ b1v, const float* __restrict__ W2m,
                               float* __restrict__ part) {
    int n = blockIdx.x * 128 + threadIdx.x;
    if (n >= VV) return;
    int v0 = blockIdx.y * 250;
    float acc = 0.f;
#pragma unroll 5
    for (int v = v0; v < v0 + 250; v++)
        acc += b1v[v] * W2m[(size_t)v * VV + n];
    part[blockIdx.y * VV + n] = acc;
}
__global__ void bias_fuse_reduce(const float* __restrict__ part, const float* __restrict__ b2v,
                                 float* __restrict__ bf) {
    int n = blockIdx.x * 128 + threadIdx.x;
    if (n >= VV) return;
    float acc = b2v[n];
#pragma unroll
    for (int y = 0; y < 32; y++) acc += part[y * VV + n];
    bf[n] = acc;
}

// ---------------- tf32 GEMM: C[M,N] = A[M,K] @ B[K,N] + bias[N] --------------
#define BM 128
#define BN 128
#define BKK 16
#define AST 20    // A smem row stride (floats) -> conflict-free fragment loads
#define BST 136   // B smem row stride (floats) -> conflict-free fragment loads

__global__ void __launch_bounds__(256) gemm_tf32(
    const float* __restrict__ A, const float* __restrict__ Bm,
    const float* __restrict__ bias, float* __restrict__ C,
    int M, int N, int K, int round_out)
{
    __shared__ __align__(16) float As[2][BM * AST];
    __shared__ __align__(16) float Bs[2][BKK * BST];

    const int nbx = (N + BN - 1) / BN;
    const int nby = M / BM;
    const int CW = 16;                     // N-chunk width for L2-friendly raster
    int bid = blockIdx.x;
    int per = CW * nby;
    int chunk = bid / per;
    int rem = bid - chunk * per;
    int cw = min(CW, nbx - chunk * CW);
    int by = rem / cw;
    int bx = chunk * CW + (rem - by * cw);
    int m0 = by * BM, n0 = bx * BN;

    int tid = threadIdx.x;
    int lane = tid & 31;
    int wid = tid >> 5;
    int wm = wid >> 2;   // 0..1  (64 rows per warp)
    int wn = wid & 3;    // 0..3  (32 cols per warp)

    uint32_t sA = (uint32_t)__cvta_generic_to_shared(&As[0][0]);
    uint32_t sB = (uint32_t)__cvta_generic_to_shared(&Bs[0][0]);

    int arow0 = tid >> 2;              int acc0c = (tid & 3) * 4;
    int arow1 = (tid + 256) >> 2;
    int brow0 = tid >> 5;              int bcc0 = (tid & 31) * 4;
    int brow1 = (tid + 256) >> 5;

    float acc[4][4][4];
#pragma unroll
    for (int a = 0; a < 4; a++)
#pragma unroll
        for (int b = 0; b < 4; b++)
#pragma unroll
            for (int c = 0; c < 4; c++) acc[a][b][c] = 0.f;

    const int KT = K / BKK;

    auto issue = [&](int kt, int buf) {
        int k0 = kt * BKK;
        {
            const float* g0 = A + (size_t)(m0 + arow0) * K + k0 + acc0c;
            const float* g1 = A + (size_t)(m0 + arow1) * K + k0 + acc0c;
            uint32_t d0 = sA + (uint32_t)(buf * BM * AST + arow0 * AST + acc0c) * 4u;
            uint32_t d1 = sA + (uint32_t)(buf * BM * AST + arow1 * AST + acc0c) * 4u;
            asm volatile("cp.async.cg.shared.global [%0],[%1],16;\n" :: "r"(d0), "l"(g0));
            asm volatile("cp.async.cg.shared.global [%0],[%1],16;\n" :: "r"(d1), "l"(g1));
        }
        {
            int n0c = n0 + bcc0;
            int gcol = (n0c < N) ? n0c : (N - 4);
            int sz = (n0c < N) ? 16 : 0;   // zero-fill OOB columns
            const float* g0 = Bm + (size_t)(k0 + brow0) * N + gcol;
            const float* g1 = Bm + (size_t)(k0 + brow1) * N + gcol;
            uint32_t d0 = sB + (uint32_t)(buf * BKK * BST + brow0 * BST + bcc0) * 4u;
            uint32_t d1 = sB + (uint32_t)(buf * BKK * BST + brow1 * BST + bcc0) * 4u;
            asm volatile("cp.async.cg.shared.global [%0],[%1],16,%2;\n" :: "r"(d0), "l"(g0), "r"(sz));
            asm volatile("cp.async.cg.shared.global [%0],[%1],16,%2;\n" :: "r"(d1), "l"(g1), "r"(sz));
        }
    };

    auto docompute = [&](int buf) {
        const float* Ab = &As[buf][0];
        const float* Bb = &Bs[buf][0];
#pragma unroll
        for (int kk = 0; kk < 2; kk++) {
            uint32_t af[4][4];
#pragma unroll
            for (int mi = 0; mi < 4; mi++) {
                int r = wm * 64 + mi * 16 + (lane >> 2);
                int c = kk * 8 + (lane & 3);
                af[mi][0] = __float_as_uint(Ab[r * AST + c]);
                af[mi][1] = __float_as_uint(Ab[(r + 8) * AST + c]);
                af[mi][2] = __float_as_uint(Ab[r * AST + c + 4]);
                af[mi][3] = __float_as_uint(Ab[(r + 8) * AST + c + 4]);
            }
            uint32_t bf[4][2];
#pragma unroll
            for (int ni = 0; ni < 4; ni++) {
                int cc = wn * 32 + ni * 8 + (lane >> 2);
                int kb = kk * 8 + (lane & 3);
                bf[ni][0] = __float_as_uint(Bb[kb * BST + cc]);
                bf[ni][1] = __float_as_uint(Bb[(kb + 4) * BST + cc]);
            }
#pragma unroll
            for (int mi = 0; mi < 4; mi++)
#pragma unroll
                for (int ni = 0; ni < 4; ni++) {
                    asm volatile(
                        "mma.sync.aligned.m16n8k8.row.col.f32.tf32.tf32.f32 "
                        "{%0,%1,%2,%3},{%4,%5,%6,%7},{%8,%9},{%0,%1,%2,%3};\n"
                        : "+f"(acc[mi][ni][0]), "+f"(acc[mi][ni][1]),
                          "+f"(acc[mi][ni][2]), "+f"(acc[mi][ni][3])
                        : "r"(af[mi][0]), "r"(af[mi][1]), "r"(af[mi][2]), "r"(af[mi][3]),
                          "r"(bf[ni][0]), "r"(bf[ni][1]));
                }
        }
    };

    issue(0, 0);
    asm volatile("cp.async.commit_group;\n");
#pragma unroll 1
    for (int kt = 0; kt < KT; kt++) {
        int cur = kt & 1;
        if (kt + 1 < KT) {
            issue(kt + 1, cur ^ 1);
            asm volatile("cp.async.commit_group;\n");
            asm volatile("cp.async.wait_group 1;\n");
        } else {
            asm volatile("cp.async.wait_group 0;\n");
        }
        __syncthreads();
        docompute(cur);
        __syncthreads();
    }

    // epilogue
#pragma unroll
    for (int mi = 0; mi < 4; mi++) {
        int r = m0 + wm * 64 + mi * 16 + (lane >> 2);
#pragma unroll
        for (int ni = 0; ni < 4; ni++) {
            int c = n0 + wn * 32 + ni * 8 + (lane & 3) * 2;
            if (c < N) {
                float b0v = bias[c], b1v = bias[c + 1];
                float v0 = acc[mi][ni][0] + b0v;
                float v1 = acc[mi][ni][1] + b1v;
                float v2 = acc[mi][ni][2] + b0v;
                float v3 = acc[mi][ni][3] + b1v;
                if (round_out) {
                    v0 = rna_tf32(v0); v1 = rna_tf32(v1);
                    v2 = rna_tf32(v2); v3 = rna_tf32(v3);
                }
                *reinterpret_cast<float2*>(&C[(size_t)r * N + c]) = make_float2(v0, v1);
                *reinterpret_cast<float2*>(&C[(size_t)(r + 8) * N + c]) = make_float2(v2, v3);
            }
        }
    }
}

// ---------------- bidirectional masked GRU scan (coalesced) -------------------
// grid (16, 2): x = batch pair, y = direction. 256 threads.
// U kept in NATIVE layout [256 k][768 cols]; threads 0..191 each own 4
// contiguous output columns -> one fully-coalesced LDG.128 per k.
__global__ void __launch_bounds__(256) gru_scan(
    const float* __restrict__ xzf, const float* __restrict__ xzb,
    const float* __restrict__ Uf, const float* __restrict__ Ub,
    const float* __restrict__ bf1, const float* __restrict__ bb1,
    const int* __restrict__ tokens, float* __restrict__ hcat)
{
    int dir = blockIdx.y;
    const float* xz = dir ? xzb : xzf;
    const float* Um = dir ? Ub : Uf;    // [256][768]
    const float* bv = dir ? bb1 : bf1;  // b[1] row (768)
    int b0 = blockIdx.x * 2;
    int tid = threadIdx.x;

    __shared__ __align__(16) float hs[2][UU];
    __shared__ __align__(16) float inner_s[2][H3];

    hs[0][tid] = 0.f; hs[1][tid] = 0.f;
    float bz = bv[tid], br = bv[UU + tid], bh = bv[2 * UU + tid];
    __syncthreads();

    // U rows as 16B chunks: chunk t of row k = cols [4t,4t+4), pre-packed f32x2 pairs
    const ulonglong2* U2 = reinterpret_cast<const ulonglong2*>(Um);

    for (int i = 0; i < SS; i++) {
        int s = dir ? (SS - 1 - i) : i;
        size_t r0 = (size_t)b0 * SS + s;
        size_t r1 = r0 + SS;

        // prefetch this step's xz rows + tokens (hidden under the matvec)
        const float* x0 = xz + r0 * H3;
        const float* x1 = xz + r1 * H3;
        float pz0 = x0[tid], pr0 = x0[UU + tid], ph0 = x0[2 * UU + tid];
        float pz1 = x1[tid], pr1 = x1[UU + tid], ph1 = x1[2 * UU + tid];
        int tk0 = tokens[r0], tk1 = tokens[r1];

        if (tid < 192) {
            unsigned long long a00 = 0, a01 = 0, a10 = 0, a11 = 0;
            const float4* hq0 = reinterpret_cast<const float4*>(hs[0]);
            const float4* hq1 = reinterpret_cast<const float4*>(hs[1]);
#pragma unroll 4
            for (int kq = 0; kq < UU / 4; kq++) {
                float4 hA = hq0[kq];
                float4 hB = hq1[kq];
                ulonglong2 u0 = U2[(size_t)(4 * kq + 0) * 192 + tid];
                ulonglong2 u1 = U2[(size_t)(4 * kq + 1) * 192 + tid];
                ulonglong2 u2 = U2[(size_t)(4 * kq + 2) * 192 + tid];
                ulonglong2 u3 = U2[(size_t)(4 * kq + 3) * 192 + tid];
                unsigned long long d;
                d = pack2(hA.x, hA.x); FMA2(a00, u0.x, d); FMA2(a01, u0.y, d);
                d = pack2(hB.x, hB.x); FMA2(a10, u0.x, d); FMA2(a11, u0.y, d);
                d = pack2(hA.y, hA.y); FMA2(a00, u1.x, d); FMA2(a01, u1.y, d);
                d = pack2(hB.y, hB.y); FMA2(a10, u1.x, d); FMA2(a11, u1.y, d);
                d = pack2(hA.z, hA.z); FMA2(a00, u2.x, d); FMA2(a01, u2.y, d);
                d = pack2(hB.z, hB.z); FMA2(a10, u2.x, d); FMA2(a11, u2.y, d);
                d = pack2(hA.w, hA.w); FMA2(a00, u3.x, d); FMA2(a01, u3.y, d);
                d = pack2(hB.w, hB.w); FMA2(a10, u3.x, d); FMA2(a11, u3.y, d);
            }
            float2 p00 = unpack2(a00), p01 = unpack2(a01);
            float2 p10 = unpack2(a10), p11 = unpack2(a11);
            reinterpret_cast<float4*>(inner_s[0])[tid] = make_float4(p00.x, p00.y, p01.x, p01.y);
            reinterpret_cast<float4*>(inner_s[1])[tid] = make_float4(p10.x, p10.y, p11.x, p11.y);
        }
        __syncthreads();

        // per-state-dim update (thread tid owns dim tid; no cross-thread hazard)
        {
            float hold0 = hs[0][tid], hold1 = hs[1][tid];

            float z0 = 1.f / (1.f + expf(-(pz0 + inner_s[0][tid] + bz)));
            float g0 = 1.f / (1.f + expf(-(pr0 + inner_s[0][UU + tid] + br)));
            float c0 = tanhf(ph0 + g0 * (inner_s[0][2 * UU + tid] + bh));
            float hn0 = z0 * hold0 + (1.f - z0) * c0;
            if (tk0 == 0) hn0 = hold0;

            float z1 = 1.f / (1.f + expf(-(pz1 + inner_s[1][tid] + bz)));
            float g1 = 1.f / (1.f + expf(-(pr1 + inner_s[1][UU + tid] + br)));
            float c1 = tanhf(ph1 + g1 * (inner_s[1][2 * UU + tid] + bh));
            float hn1 = z1 * hold1 + (1.f - z1) * c1;
            if (tk1 == 0) hn1 = hold1;

            hs[0][tid] = hn0; hs[1][tid] = hn1;
            hcat[r0 * (2 * UU) + dir * UU + tid] = rna_tf32(hn0);
            hcat[r1 * (2 * UU) + dir * UU + tid] = rna_tf32(hn1);
        }
        __syncthreads();
    }
}

// ---------------- host launcher ----------------------------------------------
extern "C" void kernel_launch(void* const* d_in, const int* in_sizes, int n_in,
                              void* d_out, int out_size)
{
    const int*   tokens = (const int*)d_in[0];
    const float* emb    = (const float*)d_in[1];
    const float* W_f    = (const float*)d_in[2];
    const float* U_f    = (const float*)d_in[3];
    const float* b_f    = (const float*)d_in[4];
    const float* W_b    = (const float*)d_in[5];
    const float* U_b    = (const float*)d_in[6];
    const float* b_b    = (const float*)d_in[7];
    const float* W1     = (const float*)d_in[8];
    const float* b1     = (const float*)d_in[9];
    const float* W2     = (const float*)d_in[10];
    const float* b2     = (const float*)d_in[11];
    float* out = (float*)d_out;

    float *x, *xzf, *xzb, *hcat, *cwf, *cwb, *cw1, *cw2, *wf, *bfv, *bpart, *zb;
    cudaGetSymbolAddress((void**)&x,     g_x);
    cudaGetSymbolAddress((void**)&xzf,   g_xzf);
    cudaGetSymbolAddress((void**)&xzb,   g_xzb);
    cudaGetSymbolAddress((void**)&hcat,  g_hcat);
    cudaGetSymbolAddress((void**)&cwf,   g_cwf);
    cudaGetSymbolAddress((void**)&cwb,   g_cwb);
    cudaGetSymbolAddress((void**)&cw1,   g_cw1);
    cudaGetSymbolAddress((void**)&cw2,   g_cw2);
    cudaGetSymbolAddress((void**)&wf,    g_wf);
    cudaGetSymbolAddress((void**)&bfv,   g_bf);
    cudaGetSymbolAddress((void**)&bpart, g_bpart);
    cudaGetSymbolAddress((void**)&zb,    g_zb);

    // 1) round weights to tf32 (rna) into scratch
    {
        int n4 = DD * H3 / 4;
        cvt_rna4<<<(n4 + 255) / 256, 256>>>((const float4*)W_f, (float4*)cwf, n4);
        cvt_rna4<<<(n4 + 255) / 256, 256>>>((const float4*)W_b, (float4*)cwb, n4);
    }
    {
        int n4 = 2 * UU * VV / 4;
        cvt_rna4<<<(n4 + 255) / 256, 256>>>((const float4*)W1, (float4*)cw1, n4);
    }
    {
        int n4 = VV * VV / 4;
        cvt_rna4<<<(n4 + 255) / 256, 256>>>((const float4*)W2, (float4*)cw2, n4);
    }

    // 2) fused output weight: Wf = W1 @ W2  [512, 8000], rounded for next GEMM
    {
        int nbx = (VV + BN - 1) / BN;           // 63
        int nby = (2 * UU) / BM;                // 4
        gemm_tf32<<<nbx * nby, 256>>>(cw1, cw2, zb, wf, 2 * UU, VV, VV, 1);
    }
    // fused bias: bf = b1 @ W2 + b2 (exact fp32, K split 32 ways)
    bias_fuse_part<<<dim3((VV + 127) / 128, 32), 128>>>(b1, W2, bpart);
    bias_fuse_reduce<<<(VV + 127) / 128, 128>>>(bpart, b2, bfv);

    // 3) embedding gather (rounded)
    embed_kernel<<<MR, DD>>>(tokens, emb, x);

    // 4) xz projections: [8192,128] @ [128,768] + b[0]
    {
        int nbx = H3 / BN, nby = MR / BM;   // 6 x 64
        gemm_tf32<<<nbx * nby, 256>>>(x, cwf, b_f, xzf, MR, H3, DD, 0);
        gemm_tf32<<<nbx * nby, 256>>>(x, cwb, b_b, xzb, MR, H3, DD, 0);
    }

    // 5) bidirectional GRU scan (U in native layout, coalesced)
    gru_scan<<<dim3(BB / 2, 2), 256>>>(xzf, xzb, U_f, U_b, b_f + H3, b_b + H3,
                                       tokens, hcat);

    // 6) logits = hcat @ Wf + bf -> output
    {
        int nbx = (VV + BN - 1) / BN, nby = MR / BM;  // 63 x 64
        gemm_tf32<<<nbx * nby, 256>>>(hcat, wf, bfv, out, MR, VV, 2 * UU, 0);
    }
}

// round 4
// speedup vs baseline: 4.9643x; 1.3445x over previous
#include <cuda_runtime.h>
#include <cstdint>

#define VV 8000
#define DD 128
#define UU 256
#define BB 32
#define SS 256
#define H3 768
#define MR 8192   // B*S

// ---------------- scratch (static device allocations; no cudaMalloc) ---------
__device__ float g_x[MR * DD];
__device__ float g_xzf[MR * H3];
__device__ float g_xzb[MR * H3];
__device__ float g_hcat[MR * 2 * UU];
__device__ float g_wf[2 * UU * VV];   // fused weight W1@W2 [512, 8000]
__device__ float g_bf[VV];            // fused bias b1@W2 + b2
__device__ float g_bpart[32 * VV];    // bias partial sums
__device__ float g_zb[VV];            // zero bias (never written; zero-init)

__device__ __forceinline__ float rna_tf32(float x) {
    uint32_t u;
    asm("cvt.rna.tf32.f32 %0, %1;" : "=r"(u) : "f"(x));
    return __uint_as_float(u);
}
__device__ __forceinline__ uint32_t rna_tf32_u(uint32_t x) {
    uint32_t u;
    asm("cvt.rna.tf32.f32 %0, %1;" : "=r"(u) : "r"(x));
    return u;
}

// packed f32x2 helpers (sm_103a)
__device__ __forceinline__ unsigned long long pack2(float x, float y) {
    unsigned long long r;
    asm("mov.b64 %0, {%1,%2};" : "=l"(r) : "f"(x), "f"(y));
    return r;
}
__device__ __forceinline__ float2 unpack2(unsigned long long v) {
    float2 r;
    asm("mov.b64 {%0,%1}, %2;" : "=f"(r.x), "=f"(r.y) : "l"(v));
    return r;
}
#define FMA2(acc, a, b) \
    asm("fma.rn.f32x2 %0, %1, %2, %0;" : "+l"(acc) : "l"(a), "l"(b))

// ---------------- embedding gather (rounded: feeds a tf32 GEMM) --------------
__global__ void embed_kernel(const int* __restrict__ tokens, const float* __restrict__ emb,
                             float* __restrict__ x) {
    int row = blockIdx.x;     // row = b*S + s
    int t = threadIdx.x;      // 0..127
    int tok = tokens[row];
    x[(size_t)row * DD + t] = rna_tf32(emb[(size_t)tok * DD + t]);
}

// ---------------- fused bias: bf[n] = b2[n] + sum_v b1[v]*W2[v][n] ------------
__global__ void bias_fuse_part(const float* __restrict__ b1v, const float* __restrict__ W2m,
                               float* __restrict__ part) {
    int n = blockIdx.x * 128 + threadIdx.x;
    if (n >= VV) return;
    int v0 = blockIdx.y * 250;
    float acc = 0.f;
#pragma unroll 5
    for (int v = v0; v < v0 + 250; v++)
        acc += b1v[v] * W2m[(size_t)v * VV + n];
    part[blockIdx.y * VV + n] = acc;
}
__global__ void bias_fuse_reduce(const float* __restrict__ part, const float* __restrict__ b2v,
                                 float* __restrict__ bf) {
    int n = blockIdx.x * 128 + threadIdx.x;
    if (n >= VV) return;
    float acc = b2v[n];
#pragma unroll
    for (int y = 0; y < 32; y++) acc += part[y * VV + n];
    bf[n] = acc;
}

// ---------------- tf32 GEMM: C[M,N] = A[M,K] @ B[K,N] + bias[N] --------------
// RA/RB: apply cvt.rna.tf32 to A/B fragments at smem load (in-GEMM rounding).
// RO: round the fp32 output to tf32 (feeds a later tf32 GEMM).
#define BM 128
#define BN 128
#define BKK 16
#define AST 20    // A smem row stride (floats) -> conflict-free fragment loads
#define BST 136   // B smem row stride (floats) -> conflict-free fragment loads

template <int RA, int RB, int RO>
__global__ void __launch_bounds__(256) gemm_tf32(
    const float* __restrict__ A, const float* __restrict__ Bm,
    const float* __restrict__ bias, float* __restrict__ C,
    int M, int N, int K)
{
    __shared__ __align__(16) float As[2][BM * AST];
    __shared__ __align__(16) float Bs[2][BKK * BST];

    const int nbx = (N + BN - 1) / BN;
    const int nby = M / BM;
    const int CW = 16;                     // N-chunk width for L2-friendly raster
    int bid = blockIdx.x;
    int per = CW * nby;
    int chunk = bid / per;
    int rem = bid - chunk * per;
    int cw = min(CW, nbx - chunk * CW);
    int by = rem / cw;
    int bx = chunk * CW + (rem - by * cw);
    int m0 = by * BM, n0 = bx * BN;

    int tid = threadIdx.x;
    int lane = tid & 31;
    int wid = tid >> 5;
    int wm = wid >> 2;   // 0..1  (64 rows per warp)
    int wn = wid & 3;    // 0..3  (32 cols per warp)

    uint32_t sA = (uint32_t)__cvta_generic_to_shared(&As[0][0]);
    uint32_t sB = (uint32_t)__cvta_generic_to_shared(&Bs[0][0]);

    int arow0 = tid >> 2;              int acc0c = (tid & 3) * 4;
    int arow1 = (tid + 256) >> 2;
    int brow0 = tid >> 5;              int bcc0 = (tid & 31) * 4;
    int brow1 = (tid + 256) >> 5;

    float acc[4][4][4];
#pragma unroll
    for (int a = 0; a < 4; a++)
#pragma unroll
        for (int b = 0; b < 4; b++)
#pragma unroll
            for (int c = 0; c < 4; c++) acc[a][b][c] = 0.f;

    const int KT = K / BKK;

    auto issue = [&](int kt, int buf) {
        int k0 = kt * BKK;
        {
            const float* g0 = A + (size_t)(m0 + arow0) * K + k0 + acc0c;
            const float* g1 = A + (size_t)(m0 + arow1) * K + k0 + acc0c;
            uint32_t d0 = sA + (uint32_t)(buf * BM * AST + arow0 * AST + acc0c) * 4u;
            uint32_t d1 = sA + (uint32_t)(buf * BM * AST + arow1 * AST + acc0c) * 4u;
            asm volatile("cp.async.cg.shared.global [%0],[%1],16;\n" :: "r"(d0), "l"(g0));
            asm volatile("cp.async.cg.shared.global [%0],[%1],16;\n" :: "r"(d1), "l"(g1));
        }
        {
            int n0c = n0 + bcc0;
            int gcol = (n0c < N) ? n0c : (N - 4);
            int sz = (n0c < N) ? 16 : 0;   // zero-fill OOB columns
            const float* g0 = Bm + (size_t)(k0 + brow0) * N + gcol;
            const float* g1 = Bm + (size_t)(k0 + brow1) * N + gcol;
            uint32_t d0 = sB + (uint32_t)(buf * BKK * BST + brow0 * BST + bcc0) * 4u;
            uint32_t d1 = sB + (uint32_t)(buf * BKK * BST + brow1 * BST + bcc0) * 4u;
            asm volatile("cp.async.cg.shared.global [%0],[%1],16,%2;\n" :: "r"(d0), "l"(g0), "r"(sz));
            asm volatile("cp.async.cg.shared.global [%0],[%1],16,%2;\n" :: "r"(d1), "l"(g1), "r"(sz));
        }
    };

    auto docompute = [&](int buf) {
        const float* Ab = &As[buf][0];
        const float* Bb = &Bs[buf][0];
#pragma unroll
        for (int kk = 0; kk < 2; kk++) {
            uint32_t af[4][4];
#pragma unroll
            for (int mi = 0; mi < 4; mi++) {
                int r = wm * 64 + mi * 16 + (lane >> 2);
                int c = kk * 8 + (lane & 3);
                af[mi][0] = __float_as_uint(Ab[r * AST + c]);
                af[mi][1] = __float_as_uint(Ab[(r + 8) * AST + c]);
                af[mi][2] = __float_as_uint(Ab[r * AST + c + 4]);
                af[mi][3] = __float_as_uint(Ab[(r + 8) * AST + c + 4]);
                if (RA) {
                    af[mi][0] = rna_tf32_u(af[mi][0]);
                    af[mi][1] = rna_tf32_u(af[mi][1]);
                    af[mi][2] = rna_tf32_u(af[mi][2]);
                    af[mi][3] = rna_tf32_u(af[mi][3]);
                }
            }
            uint32_t bf[4][2];
#pragma unroll
            for (int ni = 0; ni < 4; ni++) {
                int cc = wn * 32 + ni * 8 + (lane >> 2);
                int kb = kk * 8 + (lane & 3);
                bf[ni][0] = __float_as_uint(Bb[kb * BST + cc]);
                bf[ni][1] = __float_as_uint(Bb[(kb + 4) * BST + cc]);
                if (RB) {
                    bf[ni][0] = rna_tf32_u(bf[ni][0]);
                    bf[ni][1] = rna_tf32_u(bf[ni][1]);
                }
            }
#pragma unroll
            for (int mi = 0; mi < 4; mi++)
#pragma unroll
                for (int ni = 0; ni < 4; ni++) {
                    asm volatile(
                        "mma.sync.aligned.m16n8k8.row.col.f32.tf32.tf32.f32 "
                        "{%0,%1,%2,%3},{%4,%5,%6,%7},{%8,%9},{%0,%1,%2,%3};\n"
                        : "+f"(acc[mi][ni][0]), "+f"(acc[mi][ni][1]),
                          "+f"(acc[mi][ni][2]), "+f"(acc[mi][ni][3])
                        : "r"(af[mi][0]), "r"(af[mi][1]), "r"(af[mi][2]), "r"(af[mi][3]),
                          "r"(bf[ni][0]), "r"(bf[ni][1]));
                }
        }
    };

    issue(0, 0);
    asm volatile("cp.async.commit_group;\n");
#pragma unroll 1
    for (int kt = 0; kt < KT; kt++) {
        int cur = kt & 1;
        if (kt + 1 < KT) {
            issue(kt + 1, cur ^ 1);
            asm volatile("cp.async.commit_group;\n");
            asm volatile("cp.async.wait_group 1;\n");
        } else {
            asm volatile("cp.async.wait_group 0;\n");
        }
        __syncthreads();
        docompute(cur);
        __syncthreads();
    }

    // epilogue
#pragma unroll
    for (int mi = 0; mi < 4; mi++) {
        int r = m0 + wm * 64 + mi * 16 + (lane >> 2);
#pragma unroll
        for (int ni = 0; ni < 4; ni++) {
            int c = n0 + wn * 32 + ni * 8 + (lane & 3) * 2;
            if (c < N) {
                float b0v = bias[c], b1v = bias[c + 1];
                float v0 = acc[mi][ni][0] + b0v;
                float v1 = acc[mi][ni][1] + b1v;
                float v2 = acc[mi][ni][2] + b0v;
                float v3 = acc[mi][ni][3] + b1v;
                if (RO) {
                    v0 = rna_tf32(v0); v1 = rna_tf32(v1);
                    v2 = rna_tf32(v2); v3 = rna_tf32(v3);
                }
                *reinterpret_cast<float2*>(&C[(size_t)r * N + c]) = make_float2(v0, v1);
                *reinterpret_cast<float2*>(&C[(size_t)(r + 8) * N + c]) = make_float2(v2, v3);
            }
        }
    }
}

// ---------------- bidirectional masked GRU scan (k-split, 768 thr) -----------
// grid (16, 2): x = batch pair, y = direction. 768 threads = 24 warps.
// Thread (kc = tid/192, ct = tid%192): kc owns k-range [kc*64, kc*64+64),
// ct owns 4 contiguous output columns. Partials reduced through smem.
// h kept in smem pre-duplicated as (h,h) u64 pairs -> FMA2 operands load-ready.
__global__ void __launch_bounds__(768) gru_scan(
    const float* __restrict__ xzf, const float* __restrict__ xzb,
    const float* __restrict__ Uf, const float* __restrict__ Ub,
    const float* __restrict__ bf1, const float* __restrict__ bb1,
    const int* __restrict__ tokens, float* __restrict__ hcat)
{
    int dir = blockIdx.y;
    const float* xz = dir ? xzb : xzf;
    const float* Um = dir ? Ub : Uf;    // [256][768] native
    const float* bv = dir ? bb1 : bf1;  // b[1] row (768)
    int b0 = blockIdx.x * 2;
    int tid = threadIdx.x;
    int kc = tid / 192;        // 0..3
    int ct = tid % 192;        // 0..191

    __shared__ __align__(16) unsigned long long hsd[2][UU];  // (h,h) duplicated
    __shared__ __align__(16) float part[8][H3];              // [kc*2+b][col]

    // update-phase identity
    int ub = tid >> 8;         // 0..2 ; valid when tid < 512
    int uj = tid & 255;
    float bz = 0.f, br = 0.f, bh = 0.f;
    if (tid < 512) {
        bz = bv[uj]; br = bv[UU + uj]; bh = bv[2 * UU + uj];
        hsd[ub][uj] = 0ull;
    }
    __syncthreads();

    const ulonglong2* U2 = reinterpret_cast<const ulonglong2*>(Um);
    int k0 = kc * 64;

    for (int i = 0; i < SS; i++) {
        int s = dir ? (SS - 1 - i) : i;
        size_t rr[2];
        rr[0] = (size_t)b0 * SS + s;
        rr[1] = rr[0] + SS;

        // prefetch xz row + token for the update phase (overlaps matvec)
        float pz = 0.f, pr = 0.f, ph = 0.f; int tk = 1;
        if (tid < 512) {
            const float* xr = xz + rr[ub] * H3;
            pz = xr[uj]; pr = xr[UU + uj]; ph = xr[2 * UU + uj];
            tk = tokens[rr[ub]];
        }

        // ---- partial matvec over k-range [k0, k0+64) ----
        {
            unsigned long long a00 = 0, a01 = 0, a10 = 0, a11 = 0;
            const ulonglong2* h0 = reinterpret_cast<const ulonglong2*>(hsd[0]) + (k0 >> 1);
            const ulonglong2* h1 = reinterpret_cast<const ulonglong2*>(hsd[1]) + (k0 >> 1);
            const ulonglong2* up = U2 + (size_t)k0 * 192 + ct;
#pragma unroll 4
            for (int kk = 0; kk < 32; kk++) {
                ulonglong2 uA = up[0];
                ulonglong2 uB = up[192];
                up += 384;
                ulonglong2 hA = h0[kk];
                ulonglong2 hB = h1[kk];
                FMA2(a00, uA.x, hA.x); FMA2(a01, uA.y, hA.x);
                FMA2(a10, uA.x, hB.x); FMA2(a11, uA.y, hB.x);
                FMA2(a00, uB.x, hA.y); FMA2(a01, uB.y, hA.y);
                FMA2(a10, uB.x, hB.y); FMA2(a11, uB.y, hB.y);
            }
            float2 p00 = unpack2(a00), p01 = unpack2(a01);
            float2 p10 = unpack2(a10), p11 = unpack2(a11);
            reinterpret_cast<float4*>(part[kc * 2 + 0])[ct] = make_float4(p00.x, p00.y, p01.x, p01.y);
            reinterpret_cast<float4*>(part[kc * 2 + 1])[ct] = make_float4(p10.x, p10.y, p11.x, p11.y);
        }
        __syncthreads();

        // ---- reduce partials + gate update (threads 0..511) ----
        if (tid < 512) {
            float iz = part[0 + ub][uj]           + part[2 + ub][uj]
                     + part[4 + ub][uj]           + part[6 + ub][uj];
            float ir = part[0 + ub][UU + uj]      + part[2 + ub][UU + uj]
                     + part[4 + ub][UU + uj]      + part[6 + ub][UU + uj];
            float ih = part[0 + ub][2 * UU + uj]  + part[2 + ub][2 * UU + uj]
                     + part[4 + ub][2 * UU + uj]  + part[6 + ub][2 * UU + uj];

            float hold = ((const float*)&hsd[ub][uj])[0];
            float z = 1.f / (1.f + expf(-(pz + iz + bz)));
            float g = 1.f / (1.f + expf(-(pr + ir + br)));
            float c = tanhf(ph + g * (ih + bh));
            float hn = z * hold + (1.f - z) * c;
            if (tk == 0) hn = hold;

            hsd[ub][uj] = pack2(hn, hn);
            hcat[rr[ub] * (2 * UU) + dir * UU + uj] = rna_tf32(hn);
        }
        __syncthreads();
    }
}

// ---------------- host launcher ----------------------------------------------
extern "C" void kernel_launch(void* const* d_in, const int* in_sizes, int n_in,
                              void* d_out, int out_size)
{
    const int*   tokens = (const int*)d_in[0];
    const float* emb    = (const float*)d_in[1];
    const float* W_f    = (const float*)d_in[2];
    const float* U_f    = (const float*)d_in[3];
    const float* b_f    = (const float*)d_in[4];
    const float* W_b    = (const float*)d_in[5];
    const float* U_b    = (const float*)d_in[6];
    const float* b_b    = (const float*)d_in[7];
    const float* W1     = (const float*)d_in[8];
    const float* b1     = (const float*)d_in[9];
    const float* W2     = (const float*)d_in[10];
    const float* b2     = (const float*)d_in[11];
    float* out = (float*)d_out;

    float *x, *xzf, *xzb, *hcat, *wf, *bfv, *bpart, *zb;
    cudaGetSymbolAddress((void**)&x,     g_x);
    cudaGetSymbolAddress((void**)&xzf,   g_xzf);
    cudaGetSymbolAddress((void**)&xzb,   g_xzb);
    cudaGetSymbolAddress((void**)&hcat,  g_hcat);
    cudaGetSymbolAddress((void**)&wf,    g_wf);
    cudaGetSymbolAddress((void**)&bfv,   g_bf);
    cudaGetSymbolAddress((void**)&bpart, g_bpart);
    cudaGetSymbolAddress((void**)&zb,    g_zb);

    // 1) fused output weight: Wf = rna(W1) @ rna(W2), rounded output
    {
        int nbx = (VV + BN - 1) / BN;           // 63
        int nby = (2 * UU) / BM;                // 4
        gemm_tf32<1, 1, 1><<<nbx * nby, 256>>>(W1, W2, zb, wf, 2 * UU, VV, VV);
    }
    // fused bias: bf = b1 @ W2 + b2 (exact fp32, K split 32 ways)
    bias_fuse_part<<<dim3((VV + 127) / 128, 32), 128>>>(b1, W2, bpart);
    bias_fuse_reduce<<<(VV + 127) / 128, 128>>>(bpart, b2, bfv);

    // 2) embedding gather (rounded)
    embed_kernel<<<MR, DD>>>(tokens, emb, x);

    // 3) xz projections: [8192,128] @ rna([128,768]) + b[0]
    {
        int nbx = H3 / BN, nby = MR / BM;   // 6 x 64
        gemm_tf32<0, 1, 0><<<nbx * nby, 256>>>(x, W_f, b_f, xzf, MR, H3, DD);
        gemm_tf32<0, 1, 0><<<nbx * nby, 256>>>(x, W_b, b_b, xzb, MR, H3, DD);
    }

    // 4) bidirectional GRU scan (k-split, latency-hidden)
    gru_scan<<<dim3(BB / 2, 2), 768>>>(xzf, xzb, U_f, U_b, b_f + H3, b_b + H3,
                                       tokens, hcat);

    // 5) logits = hcat @ Wf + bf -> output
    {
        int nbx = (VV + BN - 1) / BN, nby = MR / BM;  // 63 x 64
        gemm_tf32<0, 0, 0><<<nbx * nby, 256>>>(hcat, wf, bfv, out, MR, VV, 2 * UU);
    }
}